// round 6
// baseline (speedup 1.0000x reference)
#include <cuda_runtime.h>
#include <cstdint>

#define BATCH 4096
#define NG 16
#define P1C 32
#define P1PAD 256                      // 16x16 zero-padded per channel
#define P1SZ (P1C*P1PAD)               // 8192 floats per image (padded)
#define P2C 64
#define P2SZ (P2C*7*7)                 // 3136 per image

typedef unsigned long long ull;

__device__ float g_w1[NG*9];
__device__ float g_pool1[(size_t)BATCH * P1SZ];    // ~134 MB padded
__device__ float g_pool2[(size_t)BATCH * P2SZ];    // ~51 MB

// ---- f32x2 packed helpers -------------------------------------------------
__device__ __forceinline__ ull pk2(float lo, float hi) {
    ull r; asm("mov.b64 %0, {%1,%2};" : "=l"(r) : "f"(lo), "f"(hi)); return r;
}
__device__ __forceinline__ void fma2(ull& d, ull a, ull b) {
    asm("fma.rn.f32x2 %0, %1, %2, %0;" : "+l"(d) : "l"(a), "l"(b));
}
__device__ __forceinline__ float2 upk2(ull v) {
    float2 f; asm("mov.b64 {%0,%1}, %2;" : "=f"(f.x), "=f"(f.y) : "l"(v)); return f;
}

// ---------------------------------------------------------------------------
// Kernel 0: gabor bank (16 x 3 x 3)
// ---------------------------------------------------------------------------
__global__ void gabor_kernel(const float* __restrict__ theta,
                             const float* __restrict__ sigma,
                             const float* __restrict__ gamma,
                             const float* __restrict__ lambd,
                             const float* __restrict__ psi) {
    int t = threadIdx.x;
    if (t >= NG * 9) return;
    int k = t / 9, r = t % 9, i = r / 3, j = r % 3;
    float xg = (float)i - 1.0f;
    float yg = (float)j - 1.0f;
    float th = theta[k];
    float c = cosf(th), s = sinf(th);
    float xt = xg * c + yg * s;
    float yt = -xg * s + yg * c;
    float sx = sigma[k];
    float sy = sigma[k] / gamma[k];
    float env = expf(-0.5f * (xt * xt / (sx * sx) + yt * yt / (sy * sy)));
    float car = cosf(2.0f * 3.14159265358979323846f * xt / lambd[k] + psi[k]);
    g_w1[t] = env * car;
}

// ---------------------------------------------------------------------------
// Kernel 1: conv1 + relu + pool -> zero-padded 16x16 per-channel tiles.
// ---------------------------------------------------------------------------
__global__ void __launch_bounds__(256) conv1_pool_kernel(const float* __restrict__ x) {
    __shared__ float sx[28 * 28];
    __shared__ float sw[NG * 9];
    int img = blockIdx.x;
    const float* xin = x + (size_t)img * 784;
    for (int i = threadIdx.x; i < 784; i += 256) sx[i] = xin[i];
    if (threadIdx.x < NG * 9) sw[threadIdx.x] = g_w1[threadIdx.x];
    __syncthreads();

    float* outp = g_pool1 + (size_t)img * P1SZ;

    // zero borders of all 32 padded channel tiles
    for (int i = threadIdx.x; i < P1SZ; i += 256) {
        int r = (i >> 4) & 15, c = i & 15;
        if (r == 0 || r == 15 || c == 0 || c == 15) outp[i] = 0.0f;
    }

    // identity channels (16..31): pooled relu(x), broadcast
    for (int p = threadIdx.x; p < 196; p += 256) {
        int py = p / 14, px = p % 14;
        float m = 0.0f;
        #pragma unroll
        for (int dy = 0; dy < 2; dy++)
            #pragma unroll
            for (int dx = 0; dx < 2; dx++)
                m = fmaxf(m, sx[(2 * py + dy) * 28 + (2 * px + dx)]);
        int off = (py + 1) * 16 + (px + 1);
        #pragma unroll
        for (int ch = 16; ch < 32; ch++)
            outp[ch * P1PAD + off] = m;
    }

    // gabor channels (0..15)
    for (int o = threadIdx.x; o < NG * 196; o += 256) {
        int ch = o / 196, p = o % 196;
        int py = p / 14, px = p % 14;
        float w0 = sw[ch*9+0], w1 = sw[ch*9+1], w2 = sw[ch*9+2];
        float w3 = sw[ch*9+3], w4 = sw[ch*9+4], w5 = sw[ch*9+5];
        float w6 = sw[ch*9+6], w7 = sw[ch*9+7], w8 = sw[ch*9+8];
        float m = 0.0f;
        #pragma unroll
        for (int dy = 0; dy < 2; dy++) {
            #pragma unroll
            for (int dx = 0; dx < 2; dx++) {
                int y = 2 * py + dy, xx = 2 * px + dx;
                float acc = 0.0f;
                #pragma unroll
                for (int ky = 0; ky < 3; ky++) {
                    int yy = y + ky - 1;
                    if (yy < 0 || yy >= 28) continue;
                    #pragma unroll
                    for (int kx = 0; kx < 3; kx++) {
                        int xc = xx + kx - 1;
                        if (xc < 0 || xc >= 28) continue;
                        float wv = (ky==0 ? (kx==0?w0:(kx==1?w1:w2))
                                  : ky==1 ? (kx==0?w3:(kx==1?w4:w5))
                                          : (kx==0?w6:(kx==1?w7:w8)));
                        acc += sx[yy * 28 + xc] * wv;
                    }
                }
                m = fmaxf(m, acc);
            }
        }
        outp[ch * P1PAD + (py + 1) * 16 + (px + 1)] = m;
    }
}

// ---------------------------------------------------------------------------
// Kernel 2: conv2 + bias + relu + pool.  TWO images per block, f32x2 math.
// smem: 2 padded input tiles (2*32KB) + weights (72KB) = 136KB -> 1 block/SM.
// Thread task: 4 oc x 1 pooled pos x 2 images; f32x2 packs the dx pair.
// ---------------------------------------------------------------------------
__global__ void __launch_bounds__(256) conv2_pool_kernel(const float* __restrict__ w,
                                                         const float* __restrict__ b) {
    extern __shared__ float sm[];
    float* sin0 = sm;                  // 8192
    float* sin1 = sm + 8192;           // 8192
    float* swt  = sm + 16384;          // 18432
    __shared__ float sb[64];

    int img0 = blockIdx.x * 2;
    const float* in0 = g_pool1 + (size_t)img0 * P1SZ;
    const float* in1 = in0 + P1SZ;
    for (int i = threadIdx.x; i < 2048; i += 256) {
        ((float4*)sin0)[i] = ((const float4*)in0)[i];
        ((float4*)sin1)[i] = ((const float4*)in1)[i];
    }
    for (int i = threadIdx.x; i < 18432; i += 256) swt[i] = w[i];
    if (threadIdx.x < 64) sb[threadIdx.x] = b[threadIdx.x];
    __syncthreads();

    float* out0 = g_pool2 + (size_t)img0 * P2SZ;
    float* out1 = out0 + P2SZ;

    for (int task = threadIdx.x; task < 784; task += 256) {
        int og = task / 49;
        int p  = task % 49;
        int py = p / 7, px = p % 7;
        int base = (2 * py) * 16 + 2 * px;     // padded coords (y0+1=2py)

        // acc[img][u][dy] : f32x2 over dx
        ull acc[2][4][2];
        #pragma unroll
        for (int g = 0; g < 2; g++)
            #pragma unroll
            for (int u = 0; u < 4; u++) { acc[g][u][0] = 0ULL; acc[g][u][1] = 0ULL; }

        const float* wbase = swt + og * 4 * 288;   // ((og*4+u)*32+ic)*9

        for (int ic = 0; ic < 32; ic++) {
            // patch pairs for 4 rows, both images
            ull A0[4], B0[4], C0[4], A1[4], B1[4], C1[4];
            const float* s0 = sin0 + ic * 256 + base;
            const float* s1 = sin1 + ic * 256 + base;
            #pragma unroll
            for (int r = 0; r < 4; r++) {
                float2 v0 = *(const float2*)(s0 + r * 16);
                float2 v1 = *(const float2*)(s0 + r * 16 + 2);
                A0[r] = pk2(v0.x, v0.y);
                B0[r] = pk2(v0.y, v1.x);
                C0[r] = pk2(v1.x, v1.y);
                float2 u0 = *(const float2*)(s1 + r * 16);
                float2 u1 = *(const float2*)(s1 + r * 16 + 2);
                A1[r] = pk2(u0.x, u0.y);
                B1[r] = pk2(u0.y, u1.x);
                C1[r] = pk2(u1.x, u1.y);
            }
            #pragma unroll
            for (int u = 0; u < 4; u++) {
                const float* wp = wbase + (u * 32 + ic) * 9;
                #pragma unroll
                for (int ky = 0; ky < 3; ky++) {
                    float w0 = wp[ky*3+0], w1 = wp[ky*3+1], w2 = wp[ky*3+2];
                    ull ww0 = pk2(w0, w0);
                    fma2(acc[0][u][0], A0[ky],   ww0);
                    fma2(acc[0][u][1], A0[ky+1], ww0);
                    fma2(acc[1][u][0], A1[ky],   ww0);
                    fma2(acc[1][u][1], A1[ky+1], ww0);
                    ull ww1 = pk2(w1, w1);
                    fma2(acc[0][u][0], B0[ky],   ww1);
                    fma2(acc[0][u][1], B0[ky+1], ww1);
                    fma2(acc[1][u][0], B1[ky],   ww1);
                    fma2(acc[1][u][1], B1[ky+1], ww1);
                    ull ww2 = pk2(w2, w2);
                    fma2(acc[0][u][0], C0[ky],   ww2);
                    fma2(acc[0][u][1], C0[ky+1], ww2);
                    fma2(acc[1][u][0], C1[ky],   ww2);
                    fma2(acc[1][u][1], C1[ky+1], ww2);
                }
            }
        }
        #pragma unroll
        for (int u = 0; u < 4; u++) {
            float bias = sb[og * 4 + u];
            float2 d00 = upk2(acc[0][u][0]);
            float2 d01 = upk2(acc[0][u][1]);
            float m0 = fmaxf(fmaxf(d00.x, d00.y), fmaxf(d01.x, d01.y)) + bias;
            out0[(og * 4 + u) * 49 + p] = fmaxf(m0, 0.0f);
            float2 d10 = upk2(acc[1][u][0]);
            float2 d11 = upk2(acc[1][u][1]);
            float m1 = fmaxf(fmaxf(d10.x, d10.y), fmaxf(d11.x, d11.y)) + bias;
            out1[(og * 4 + u) * 49 + p] = fmaxf(m1, 0.0f);
        }
    }
}

// ---------------------------------------------------------------------------
// Kernel 3: fused fc1 (3136->128) + relu + fc2 (128->10).
// BM=16, BN=128, BK=32, 256 threads, thread tile 2x4, f32x2. grid = 256.
// ---------------------------------------------------------------------------
#define FC_BM 16
__global__ void __launch_bounds__(256) fc_kernel(const float* __restrict__ w1,
                                                 const float* __restrict__ b1,
                                                 const float* __restrict__ w2,
                                                 const float* __restrict__ b2,
                                                 float* __restrict__ out) {
    __shared__ float sA[FC_BM * 32];      // 512
    __shared__ float sB[32 * 128];        // 4096
    __shared__ float sC[FC_BM * 132];     // padded
    __shared__ float sw2[10 * 128];
    __shared__ float sb1[128];

    int t  = threadIdx.x;
    int m0 = blockIdx.x * FC_BM;
    int cg = t & 31;          // col group: cols cg*4..+3
    int rg = t >> 5;          // row group: rows rg*2, rg*2+1

    for (int i = t; i < 1280; i += 256) sw2[i] = w2[i];
    if (t < 128) sb1[t] = b1[t];

    ull acc[2][2];
    acc[0][0] = acc[0][1] = acc[1][0] = acc[1][1] = 0ULL;

    const float* A = g_pool2 + (size_t)m0 * 3136;
    int bn = t >> 1;                  // 0..127
    int bk = (t & 1) * 16;

    for (int k0 = 0; k0 < 3136; k0 += 32) {
        __syncthreads();
        // A tile (coalesced)
        {
            int idx = t;
            sA[idx] = A[(idx >> 5) * 3136 + k0 + (idx & 31)];
            idx = t + 256;
            sA[idx] = A[(idx >> 5) * 3136 + k0 + (idx & 31)];
        }
        // B tile via float4 loads, scalar scatter to [kk][n]
        {
            const float* wp = w1 + (size_t)bn * 3136 + k0 + bk;
            #pragma unroll
            for (int i = 0; i < 4; i++) {
                float4 v = *(const float4*)(wp + i * 4);
                int kk = bk + i * 4;
                sB[(kk + 0) * 128 + bn] = v.x;
                sB[(kk + 1) * 128 + bn] = v.y;
                sB[(kk + 2) * 128 + bn] = v.z;
                sB[(kk + 3) * 128 + bn] = v.w;
            }
        }
        __syncthreads();
        #pragma unroll
        for (int kk = 0; kk < 32; kk += 2) {
            float2 a0 = *(const float2*)&sA[(rg * 2 + 0) * 32 + kk];
            float2 a1 = *(const float2*)&sA[(rg * 2 + 1) * 32 + kk];
            #pragma unroll
            for (int q = 0; q < 2; q++) {
                float4 bv = *(const float4*)&sB[(kk + q) * 128 + cg * 4];
                ull b01 = pk2(bv.x, bv.y);
                ull b23 = pk2(bv.z, bv.w);
                float av0 = q ? a0.y : a0.x;
                float av1 = q ? a1.y : a1.x;
                ull pa0 = pk2(av0, av0);
                ull pa1 = pk2(av1, av1);
                fma2(acc[0][0], pa0, b01);
                fma2(acc[0][1], pa0, b23);
                fma2(acc[1][0], pa1, b01);
                fma2(acc[1][1], pa1, b23);
            }
        }
    }
    __syncthreads();
    // bias + relu -> sC
    #pragma unroll
    for (int i = 0; i < 2; i++) {
        int row = rg * 2 + i;
        float2 c0 = upk2(acc[i][0]);
        float2 c1 = upk2(acc[i][1]);
        int col = cg * 4;
        sC[row * 132 + col + 0] = fmaxf(c0.x + sb1[col + 0], 0.0f);
        sC[row * 132 + col + 1] = fmaxf(c0.y + sb1[col + 1], 0.0f);
        sC[row * 132 + col + 2] = fmaxf(c1.x + sb1[col + 2], 0.0f);
        sC[row * 132 + col + 3] = fmaxf(c1.y + sb1[col + 3], 0.0f);
    }
    __syncthreads();
    // fc2 epilogue: 16 rows x 10 outputs
    for (int task = t; task < FC_BM * 10; task += 256) {
        int row = task / 10, o = task % 10;
        const float* wr = sw2 + o * 128;
        float s = 0.0f;
        #pragma unroll 16
        for (int k = 0; k < 128; k++) s += sC[row * 132 + k] * wr[k];
        out[(size_t)(m0 + row) * 10 + o] = s + b2[o];
    }
}

// ---------------------------------------------------------------------------
extern "C" void kernel_launch(void* const* d_in, const int* in_sizes, int n_in,
                              void* d_out, int out_size) {
    const float* x       = (const float*)d_in[0];
    const float* theta   = (const float*)d_in[1];
    const float* sigma   = (const float*)d_in[2];
    const float* gamma   = (const float*)d_in[3];
    const float* lambd   = (const float*)d_in[4];
    const float* psi     = (const float*)d_in[5];
    const float* conv2_w = (const float*)d_in[6];
    const float* conv2_b = (const float*)d_in[7];
    const float* fc1_w   = (const float*)d_in[8];
    const float* fc1_b   = (const float*)d_in[9];
    const float* fc2_w   = (const float*)d_in[10];
    const float* fc2_b   = (const float*)d_in[11];
    float* out = (float*)d_out;

    static bool attr_set = false;
    if (!attr_set) {
        cudaFuncSetAttribute(conv2_pool_kernel,
                             cudaFuncAttributeMaxDynamicSharedMemorySize,
                             (16384 + 18432) * (int)sizeof(float));
        attr_set = true;
    }

    gabor_kernel<<<1, 160>>>(theta, sigma, gamma, lambd, psi);
    conv1_pool_kernel<<<BATCH, 256>>>(x);
    conv2_pool_kernel<<<BATCH / 2, 256, (16384 + 18432) * sizeof(float)>>>(conv2_w, conv2_b);
    fc_kernel<<<BATCH / FC_BM, 256>>>(fc1_w, fc1_b, fc2_w, fc2_b, out);
}

// round 7
// speedup vs baseline: 1.8873x; 1.8873x over previous
#include <cuda_runtime.h>
#include <cstdint>

#define BATCH 4096
#define IMGS 8                       // images per conv block
#define NBLK (BATCH/IMGS)            // 512
#define TSTRIDE 4356                 // floats per image tile (17*256 + 4 pad -> bank skew)
#define TILEF (IMGS*TSTRIDE)         // 34848 floats
#define WCNT (64*17*9)               // 9792 dup-packed weights

typedef unsigned long long ull;

__device__ float g_w1[16*9];                         // gabor bank
__device__ __align__(16) ull g_w2p[WCNT];            // conv2 weights, dup-packed (v,v), identity-collapsed
__device__ float g_pool2[(size_t)BATCH * 3136];      // conv2 output (fc input)

// ---- f32x2 packed helpers -------------------------------------------------
__device__ __forceinline__ ull pk2(float lo, float hi) {
    ull r; asm("mov.b64 %0, {%1,%2};" : "=l"(r) : "f"(lo), "f"(hi)); return r;
}
__device__ __forceinline__ ull dup2(float v) {
    unsigned u = __float_as_uint(v); return (ull)u | ((ull)u << 32);
}
__device__ __forceinline__ void fma2(ull& d, ull a, ull b) {
    asm("fma.rn.f32x2 %0, %1, %2, %0;" : "+l"(d) : "l"(a), "l"(b));
}
__device__ __forceinline__ float2 upk2(ull v) {
    float2 f; asm("mov.b64 {%0,%1}, %2;" : "=f"(f.x), "=f"(f.y) : "l"(v)); return f;
}
__device__ __forceinline__ void cpasync16(unsigned saddr, const void* g) {
    asm volatile("cp.async.cg.shared.global [%0], [%1], 16;" :: "r"(saddr), "l"(g));
}

// ---------------------------------------------------------------------------
// Kernel 0: gabor bank (16 x 3 x 3)
// ---------------------------------------------------------------------------
__global__ void gabor_kernel(const float* __restrict__ theta,
                             const float* __restrict__ sigma,
                             const float* __restrict__ gamma,
                             const float* __restrict__ lambd,
                             const float* __restrict__ psi) {
    int t = threadIdx.x;
    if (t >= 16 * 9) return;
    int k = t / 9, r = t % 9, i = r / 3, j = r % 3;
    float xg = (float)i - 1.0f;
    float yg = (float)j - 1.0f;
    float th = theta[k];
    float c = cosf(th), s = sinf(th);
    float xt = xg * c + yg * s;
    float yt = -xg * s + yg * c;
    float sx = sigma[k];
    float sy = sigma[k] / gamma[k];
    float env = expf(-0.5f * (xt * xt / (sx * sx) + yt * yt / (sy * sy)));
    float car = cosf(2.0f * 3.14159265358979323846f * xt / lambd[k] + psi[k]);
    g_w1[t] = env * car;
}

// ---------------------------------------------------------------------------
// Kernel 0b: conv2 weight prep — collapse identity channels 16..31 into one
// effective channel, store dup-packed (v,v) ulls in layout [(oc*17+ic)*9+k].
// ---------------------------------------------------------------------------
__global__ void prep_w2_kernel(const float* __restrict__ w) {
    int i = blockIdx.x * blockDim.x + threadIdx.x;    // over 64*9 = 576
    if (i >= 576) return;
    int oc = i / 9, k = i % 9;
    #pragma unroll 4
    for (int ic = 0; ic < 16; ic++) {
        float v = w[(oc * 32 + ic) * 9 + k];
        g_w2p[(oc * 17 + ic) * 9 + k] = dup2(v);
    }
    float s = 0.0f;
    #pragma unroll
    for (int j = 16; j < 32; j++) s += w[(oc * 32 + j) * 9 + k];
    g_w2p[(oc * 17 + 16) * 9 + k] = dup2(s);
}

// ---------------------------------------------------------------------------
// Kernel 1: FUSED conv1+pool -> smem tiles -> conv2+bias+relu+pool -> g_pool2.
// 8 images/block, 256 threads, 512 blocks.
// conv2: og = t>>3 (2 oc), img = t&7, loop py 0..6  (1792 tasks = 256*7 exact)
// ---------------------------------------------------------------------------
__global__ void __launch_bounds__(256) conv12_kernel(const float* __restrict__ x,
                                                     const float* __restrict__ b2c) {
    extern __shared__ float sm[];
    float* tiles = sm;                                // 34848 floats
    ull*   swt   = (ull*)(sm + TILEF);                // 9792 ull (16B aligned)
    __shared__ ull sw1d[144];

    int t = threadIdx.x;
    int imgbase = blockIdx.x * IMGS;

    // prefetch conv2 weights (78336B = 4896 x 16B) — overlaps conv1
    {
        unsigned sw_s = (unsigned)__cvta_generic_to_shared(swt);
        const char* gsrc = (const char*)g_w2p;
        for (int i = t; i < 4896; i += 256)
            cpasync16(sw_s + i * 16, gsrc + (size_t)i * 16);
        asm volatile("cp.async.commit_group;");
    }
    // zero tile region (borders must be 0; interior overwritten by conv1)
    float4 z4 = make_float4(0.f, 0.f, 0.f, 0.f);
    for (int i = t; i < TILEF / 4; i += 256) ((float4*)tiles)[i] = z4;
    if (t < 144) sw1d[t] = dup2(g_w1[t]);
    __syncthreads();

    // ---- conv1 + relu + pool into smem tiles (1568 tasks) ----
    for (int task = t; task < IMGS * 196; task += 256) {
        int img = task / 196, p = task - img * 196;
        int py = p / 14, px = p - py * 14;
        const float* xin = x + (size_t)(imgbase + img) * 784;
        float patch[4][4];
        #pragma unroll
        for (int rr = 0; rr < 4; rr++) {
            int r = 2 * py - 1 + rr;
            bool rok = (r >= 0) && (r < 28);
            #pragma unroll
            for (int cc = 0; cc < 4; cc++) {
                int c = 2 * px - 1 + cc;
                patch[rr][cc] = (rok && c >= 0 && c < 28) ? __ldg(xin + r * 28 + c) : 0.0f;
            }
        }
        float* tp = tiles + img * TSTRIDE + (py + 1) * 16 + (px + 1);
        // identity effective channel (ic=16): pooled relu(x)
        float mi = fmaxf(fmaxf(patch[1][1], patch[1][2]), fmaxf(patch[2][1], patch[2][2]));
        tp[16 * 256] = fmaxf(mi, 0.0f);
        // dx pairs shared across all 16 gabor channels
        ull P[4][3];
        #pragma unroll
        for (int rr = 0; rr < 4; rr++)
            #pragma unroll
            for (int kx = 0; kx < 3; kx++)
                P[rr][kx] = pk2(patch[rr][kx], patch[rr][kx + 1]);
        #pragma unroll 4
        for (int ch = 0; ch < 16; ch++) {
            const ull* wc = sw1d + ch * 9;
            ull a0 = 0ULL, a1 = 0ULL;
            #pragma unroll
            for (int ky = 0; ky < 3; ky++) {
                #pragma unroll
                for (int kx = 0; kx < 3; kx++) {
                    ull w = wc[ky * 3 + kx];
                    fma2(a0, P[ky][kx], w);
                    fma2(a1, P[ky + 1][kx], w);
                }
            }
            float2 f0 = upk2(a0), f1 = upk2(a1);
            float mm = fmaxf(fmaxf(f0.x, f0.y), fmaxf(f1.x, f1.y));
            tp[ch * 256] = fmaxf(mm, 0.0f);
        }
    }
    asm volatile("cp.async.wait_group 0;");
    __syncthreads();

    // ---- conv2 (17 eff ic) + bias + relu + pool ----
    int og = t >> 3, img = t & 7;
    int oc0 = og * 2;
    float bb0 = b2c[oc0], bb1 = b2c[oc0 + 1];
    const float* tin = tiles + img * TSTRIDE;
    float* outp = g_pool2 + (size_t)(imgbase + img) * 3136;
    const ull* wb0 = swt + (size_t)(oc0 * 17) * 9;
    const ull* wb1 = swt + (size_t)((oc0 + 1) * 17) * 9;

    for (int py = 0; py < 7; py++) {
        ull acc[2][2][7];
        #pragma unroll
        for (int a = 0; a < 2; a++)
            #pragma unroll
            for (int d = 0; d < 2; d++)
                #pragma unroll
                for (int px = 0; px < 7; px++) acc[a][d][px] = 0ULL;

        for (int ic = 0; ic < 17; ic++) {
            ull W0[9], W1[9];
            #pragma unroll
            for (int j = 0; j < 9; j++) { W0[j] = wb0[ic * 9 + j]; W1[j] = wb1[ic * 9 + j]; }
            const float* rowp = tin + ic * 256 + 2 * py * 16;

            #pragma unroll
            for (int rr = 0; rr < 4; rr++) {
                float4 q0 = *(const float4*)(rowp + rr * 16 + 0);
                float4 q1 = *(const float4*)(rowp + rr * 16 + 4);
                float4 q2 = *(const float4*)(rowp + rr * 16 + 8);
                float4 q3 = *(const float4*)(rowp + rr * 16 + 12);
                ull E[8], O[7];
                E[0] = pk2(q0.x, q0.y); E[1] = pk2(q0.z, q0.w);
                E[2] = pk2(q1.x, q1.y); E[3] = pk2(q1.z, q1.w);
                E[4] = pk2(q2.x, q2.y); E[5] = pk2(q2.z, q2.w);
                E[6] = pk2(q3.x, q3.y); E[7] = pk2(q3.z, q3.w);
                O[0] = pk2(q0.y, q0.z); O[1] = pk2(q0.w, q1.x);
                O[2] = pk2(q1.y, q1.z); O[3] = pk2(q1.w, q2.x);
                O[4] = pk2(q2.y, q2.z); O[5] = pk2(q2.w, q3.x);
                O[6] = pk2(q3.y, q3.z);

                #define APPLY(dy, ky) do {                                          \
                    ull wA0 = W0[(ky)*3+0], wA1 = W1[(ky)*3+0];                     \
                    ull wBq0 = W0[(ky)*3+1], wBq1 = W1[(ky)*3+1];                   \
                    ull wC0 = W0[(ky)*3+2], wC1 = W1[(ky)*3+2];                     \
                    _Pragma("unroll")                                               \
                    for (int px = 0; px < 7; px++) {                                \
                        fma2(acc[0][dy][px], E[px],   wA0);                         \
                        fma2(acc[1][dy][px], E[px],   wA1);                         \
                        fma2(acc[0][dy][px], O[px],   wBq0);                        \
                        fma2(acc[1][dy][px], O[px],   wBq1);                        \
                        fma2(acc[0][dy][px], E[px+1], wC0);                         \
                        fma2(acc[1][dy][px], E[px+1], wC1);                         \
                    }                                                               \
                } while (0)

                if (rr <= 2) APPLY(0, rr);        // dy=0, ky=rr
                if (rr >= 1) APPLY(1, rr - 1);    // dy=1, ky=rr-1
                #undef APPLY
            }
        }
        // pool max over (dy,dx) + bias + relu
        #pragma unroll
        for (int px = 0; px < 7; px++) {
            float2 a0 = upk2(acc[0][0][px]), a1 = upk2(acc[0][1][px]);
            float m0 = fmaxf(fmaxf(a0.x, a0.y), fmaxf(a1.x, a1.y));
            outp[oc0 * 49 + py * 7 + px] = fmaxf(m0 + bb0, 0.0f);
            float2 c0 = upk2(acc[1][0][px]), c1 = upk2(acc[1][1][px]);
            float m1 = fmaxf(fmaxf(c0.x, c0.y), fmaxf(c1.x, c1.y));
            outp[(oc0 + 1) * 49 + py * 7 + px] = fmaxf(m1 + bb1, 0.0f);
        }
    }
}

// ---------------------------------------------------------------------------
// Kernel 2: fused fc1 (3136->128) + relu + fc2 (128->10).
// BM=32 -> grid 128 (one wave). BK=32, 256 threads, tile 4x4, f32x2,
// register-prefetch double buffering.
// ---------------------------------------------------------------------------
#define FCBM 32
__global__ void __launch_bounds__(256) fc_kernel(const float* __restrict__ w1,
                                                 const float* __restrict__ b1,
                                                 const float* __restrict__ w2,
                                                 const float* __restrict__ b2,
                                                 float* __restrict__ out) {
    __shared__ float sAT[32 * 36];     // [kk][row], stride 36 (16B-aligned reads)
    __shared__ float sB[32 * 132];     // [kk][n],  stride 132; reused as sC
    __shared__ float sw2[10 * 128];
    __shared__ float sb1v[128];

    int t  = threadIdx.x;
    int m0 = blockIdx.x * FCBM;
    int rg = t >> 5;                   // warp id -> rows rg*4..+3 (warp-uniform)
    int cg = t & 31;                   // cols cg*4..+3

    for (int i = t; i < 1280; i += 256) sw2[i] = w2[i];
    if (t < 128) sb1v[t] = b1[t];

    int arow = t >> 3, akk = (t & 7) * 4;
    int bn   = t >> 1, bkk = (t & 1) * 16;
    const float* Ap = g_pool2 + (size_t)(m0 + arow) * 3136 + akk;
    const float* Bp = w1 + (size_t)bn * 3136 + bkk;

    ull acc[4][2];
    #pragma unroll
    for (int i = 0; i < 4; i++) { acc[i][0] = 0ULL; acc[i][1] = 0ULL; }

    float4 ra  = *(const float4*)(Ap);
    float4 rb0 = *(const float4*)(Bp);
    float4 rb1 = *(const float4*)(Bp + 4);
    float4 rb2 = *(const float4*)(Bp + 8);
    float4 rb3 = *(const float4*)(Bp + 12);

    for (int k0 = 0; k0 < 3136; k0 += 32) {
        // commit prefetched tile to smem
        sAT[(akk + 0) * 36 + arow] = ra.x;
        sAT[(akk + 1) * 36 + arow] = ra.y;
        sAT[(akk + 2) * 36 + arow] = ra.z;
        sAT[(akk + 3) * 36 + arow] = ra.w;
        sB[(bkk + 0)  * 132 + bn] = rb0.x;  sB[(bkk + 1)  * 132 + bn] = rb0.y;
        sB[(bkk + 2)  * 132 + bn] = rb0.z;  sB[(bkk + 3)  * 132 + bn] = rb0.w;
        sB[(bkk + 4)  * 132 + bn] = rb1.x;  sB[(bkk + 5)  * 132 + bn] = rb1.y;
        sB[(bkk + 6)  * 132 + bn] = rb1.z;  sB[(bkk + 7)  * 132 + bn] = rb1.w;
        sB[(bkk + 8)  * 132 + bn] = rb2.x;  sB[(bkk + 9)  * 132 + bn] = rb2.y;
        sB[(bkk + 10) * 132 + bn] = rb2.z;  sB[(bkk + 11) * 132 + bn] = rb2.w;
        sB[(bkk + 12) * 132 + bn] = rb3.x;  sB[(bkk + 13) * 132 + bn] = rb3.y;
        sB[(bkk + 14) * 132 + bn] = rb3.z;  sB[(bkk + 15) * 132 + bn] = rb3.w;
        __syncthreads();
        // prefetch next k-block (overlaps compute)
        if (k0 + 32 < 3136) {
            ra  = *(const float4*)(Ap + k0 + 32);
            rb0 = *(const float4*)(Bp + k0 + 32);
            rb1 = *(const float4*)(Bp + k0 + 36);
            rb2 = *(const float4*)(Bp + k0 + 40);
            rb3 = *(const float4*)(Bp + k0 + 44);
        }
        #pragma unroll
        for (int kk = 0; kk < 32; kk++) {
            float4 av = *(const float4*)&sAT[kk * 36 + rg * 4];   // broadcast
            float4 bv = *(const float4*)&sB[kk * 132 + cg * 4];
            ull b01 = pk2(bv.x, bv.y), b23 = pk2(bv.z, bv.w);
            ull a;
            a = dup2(av.x); fma2(acc[0][0], a, b01); fma2(acc[0][1], a, b23);
            a = dup2(av.y); fma2(acc[1][0], a, b01); fma2(acc[1][1], a, b23);
            a = dup2(av.z); fma2(acc[2][0], a, b01); fma2(acc[2][1], a, b23);
            a = dup2(av.w); fma2(acc[3][0], a, b01); fma2(acc[3][1], a, b23);
        }
        __syncthreads();
    }

    // relu(fc1) -> sC (reuse sB, stride 132)
    float* sC = sB;
    #pragma unroll
    for (int i = 0; i < 4; i++) {
        int row = rg * 4 + i, col = cg * 4;
        float2 c0 = upk2(acc[i][0]);
        float2 c1 = upk2(acc[i][1]);
        sC[row * 132 + col + 0] = fmaxf(c0.x + sb1v[col + 0], 0.0f);
        sC[row * 132 + col + 1] = fmaxf(c0.y + sb1v[col + 1], 0.0f);
        sC[row * 132 + col + 2] = fmaxf(c1.x + sb1v[col + 2], 0.0f);
        sC[row * 132 + col + 3] = fmaxf(c1.y + sb1v[col + 3], 0.0f);
    }
    __syncthreads();
    // fc2 epilogue: 32 rows x 10 outputs
    for (int task = t; task < FCBM * 10; task += 256) {
        int row = task / 10, o = task % 10;
        const float* wr = sw2 + o * 128;
        float s = 0.0f;
        #pragma unroll 16
        for (int k = 0; k < 128; k++) s += sC[row * 132 + k] * wr[k];
        out[(size_t)(m0 + row) * 10 + o] = s + b2[o];
    }
}

// ---------------------------------------------------------------------------
extern "C" void kernel_launch(void* const* d_in, const int* in_sizes, int n_in,
                              void* d_out, int out_size) {
    const float* x       = (const float*)d_in[0];
    const float* theta   = (const float*)d_in[1];
    const float* sigma   = (const float*)d_in[2];
    const float* gamma   = (const float*)d_in[3];
    const float* lambd   = (const float*)d_in[4];
    const float* psi     = (const float*)d_in[5];
    const float* conv2_w = (const float*)d_in[6];
    const float* conv2_b = (const float*)d_in[7];
    const float* fc1_w   = (const float*)d_in[8];
    const float* fc1_b   = (const float*)d_in[9];
    const float* fc2_w   = (const float*)d_in[10];
    const float* fc2_b   = (const float*)d_in[11];
    float* out = (float*)d_out;

    const int CONV_SMEM = TILEF * 4 + WCNT * 8;   // 139392 + 78336 = 217728 B

    static bool attr_set = false;
    if (!attr_set) {
        cudaFuncSetAttribute(conv12_kernel,
                             cudaFuncAttributeMaxDynamicSharedMemorySize, CONV_SMEM);
        attr_set = true;
    }

    gabor_kernel<<<1, 160>>>(theta, sigma, gamma, lambd, psi);
    prep_w2_kernel<<<3, 256>>>(conv2_w);
    conv12_kernel<<<NBLK, 256, CONV_SMEM>>>(x, conv2_b);
    fc_kernel<<<BATCH / FCBM, 256>>>(fc1_w, fc1_b, fc2_w, fc2_b, out);
}

// round 8
// speedup vs baseline: 1.8922x; 1.0026x over previous
#include <cuda_runtime.h>
#include <cstdint>

#define BATCH 4096
#define IMGS 8                       // images per conv block
#define NBLK (BATCH/IMGS)            // 512
#define TSTRIDE 4356                 // floats per image tile (17*256 + 4 pad -> bank skew)
#define TILEF (IMGS*TSTRIDE)         // 34848 floats
#define WCNT (64*17*9)               // 9792 dup-packed weights

typedef unsigned long long ull;

__device__ float g_w1[16*9];                         // gabor bank
__device__ __align__(16) ull g_w2p[WCNT];            // conv2 weights, dup-packed (v,v), identity-collapsed
__device__ float g_pool2[(size_t)BATCH * 3136];      // conv2 output (fc input)

// ---- f32x2 packed helpers -------------------------------------------------
__device__ __forceinline__ ull pk2(float lo, float hi) {
    ull r; asm("mov.b64 %0, {%1,%2};" : "=l"(r) : "f"(lo), "f"(hi)); return r;
}
__device__ __forceinline__ ull dup2(float v) {
    unsigned u = __float_as_uint(v); return (ull)u | ((ull)u << 32);
}
__device__ __forceinline__ void fma2(ull& d, ull a, ull b) {
    asm("fma.rn.f32x2 %0, %1, %2, %0;" : "+l"(d) : "l"(a), "l"(b));
}
__device__ __forceinline__ float2 upk2(ull v) {
    float2 f; asm("mov.b64 {%0,%1}, %2;" : "=f"(f.x), "=f"(f.y) : "l"(v)); return f;
}
__device__ __forceinline__ void cpasync16(unsigned saddr, const void* g) {
    asm volatile("cp.async.cg.shared.global [%0], [%1], 16;" :: "r"(saddr), "l"(g));
}

// ---------------------------------------------------------------------------
// Kernel 0: gabor bank (16 x 3 x 3)
// ---------------------------------------------------------------------------
__global__ void gabor_kernel(const float* __restrict__ theta,
                             const float* __restrict__ sigma,
                             const float* __restrict__ gamma,
                             const float* __restrict__ lambd,
                             const float* __restrict__ psi) {
    int t = threadIdx.x;
    if (t >= 16 * 9) return;
    int k = t / 9, r = t % 9, i = r / 3, j = r % 3;
    float xg = (float)i - 1.0f;
    float yg = (float)j - 1.0f;
    float th = theta[k];
    float c = cosf(th), s = sinf(th);
    float xt = xg * c + yg * s;
    float yt = -xg * s + yg * c;
    float sx = sigma[k];
    float sy = sigma[k] / gamma[k];
    float env = expf(-0.5f * (xt * xt / (sx * sx) + yt * yt / (sy * sy)));
    float car = cosf(2.0f * 3.14159265358979323846f * xt / lambd[k] + psi[k]);
    g_w1[t] = env * car;
}

// ---------------------------------------------------------------------------
// Kernel 0b: conv2 weight prep — collapse identity channels 16..31 into one
// effective channel, store dup-packed (v,v) ulls in layout [(oc*17+ic)*9+k].
// ---------------------------------------------------------------------------
__global__ void prep_w2_kernel(const float* __restrict__ w) {
    int i = blockIdx.x * blockDim.x + threadIdx.x;    // over 64*9 = 576
    if (i >= 576) return;
    int oc = i / 9, k = i % 9;
    #pragma unroll 4
    for (int ic = 0; ic < 16; ic++) {
        float v = w[(oc * 32 + ic) * 9 + k];
        g_w2p[(oc * 17 + ic) * 9 + k] = dup2(v);
    }
    float s = 0.0f;
    #pragma unroll
    for (int j = 16; j < 32; j++) s += w[(oc * 32 + j) * 9 + k];
    g_w2p[(oc * 17 + 16) * 9 + k] = dup2(s);
}

// ---------------------------------------------------------------------------
// Kernel 1: FUSED conv1+pool -> smem tiles -> conv2+bias+relu+pool -> g_pool2.
// 8 images/block, 256 threads, 512 blocks.
// conv2: og = t>>3 (2 oc), img = t&7, loop py 0..6  (1792 tasks = 256*7 exact)
// ---------------------------------------------------------------------------
__global__ void __launch_bounds__(256) conv12_kernel(const float* __restrict__ x,
                                                     const float* __restrict__ b2c) {
    extern __shared__ float sm[];
    float* tiles = sm;                                // 34848 floats
    ull*   swt   = (ull*)(sm + TILEF);                // 9792 ull (16B aligned)
    __shared__ ull sw1d[144];

    int t = threadIdx.x;
    int imgbase = blockIdx.x * IMGS;

    // prefetch conv2 weights (78336B = 4896 x 16B) — overlaps conv1
    {
        unsigned sw_s = (unsigned)__cvta_generic_to_shared(swt);
        const char* gsrc = (const char*)g_w2p;
        for (int i = t; i < 4896; i += 256)
            cpasync16(sw_s + i * 16, gsrc + (size_t)i * 16);
        asm volatile("cp.async.commit_group;");
    }
    // zero tile region (borders must be 0; interior overwritten by conv1)
    float4 z4 = make_float4(0.f, 0.f, 0.f, 0.f);
    for (int i = t; i < TILEF / 4; i += 256) ((float4*)tiles)[i] = z4;
    if (t < 144) sw1d[t] = dup2(g_w1[t]);
    __syncthreads();

    // ---- conv1 + relu + pool into smem tiles (1568 tasks) ----
    for (int task = t; task < IMGS * 196; task += 256) {
        int img = task / 196, p = task - img * 196;
        int py = p / 14, px = p - py * 14;
        const float* xin = x + (size_t)(imgbase + img) * 784;
        float patch[4][4];
        #pragma unroll
        for (int rr = 0; rr < 4; rr++) {
            int r = 2 * py - 1 + rr;
            bool rok = (r >= 0) && (r < 28);
            #pragma unroll
            for (int cc = 0; cc < 4; cc++) {
                int c = 2 * px - 1 + cc;
                patch[rr][cc] = (rok && c >= 0 && c < 28) ? __ldg(xin + r * 28 + c) : 0.0f;
            }
        }
        float* tp = tiles + img * TSTRIDE + (py + 1) * 16 + (px + 1);
        // identity effective channel (ic=16): pooled relu(x)
        float mi = fmaxf(fmaxf(patch[1][1], patch[1][2]), fmaxf(patch[2][1], patch[2][2]));
        tp[16 * 256] = fmaxf(mi, 0.0f);
        // dx pairs shared across all 16 gabor channels
        ull P[4][3];
        #pragma unroll
        for (int rr = 0; rr < 4; rr++)
            #pragma unroll
            for (int kx = 0; kx < 3; kx++)
                P[rr][kx] = pk2(patch[rr][kx], patch[rr][kx + 1]);
        #pragma unroll 4
        for (int ch = 0; ch < 16; ch++) {
            const ull* wc = sw1d + ch * 9;
            ull a0 = 0ULL, a1 = 0ULL;
            #pragma unroll
            for (int ky = 0; ky < 3; ky++) {
                #pragma unroll
                for (int kx = 0; kx < 3; kx++) {
                    ull w = wc[ky * 3 + kx];
                    fma2(a0, P[ky][kx], w);
                    fma2(a1, P[ky + 1][kx], w);
                }
            }
            float2 f0 = upk2(a0), f1 = upk2(a1);
            float mm = fmaxf(fmaxf(f0.x, f0.y), fmaxf(f1.x, f1.y));
            tp[ch * 256] = fmaxf(mm, 0.0f);
        }
    }
    asm volatile("cp.async.wait_group 0;");
    __syncthreads();

    // ---- conv2 (17 eff ic) + bias + relu + pool ----
    int og = t >> 3, img = t & 7;
    int oc0 = og * 2;
    float bb0 = b2c[oc0], bb1 = b2c[oc0 + 1];
    const float* tin = tiles + img * TSTRIDE;
    float* outp = g_pool2 + (size_t)(imgbase + img) * 3136;
    const ull* wb0 = swt + (size_t)(oc0 * 17) * 9;
    const ull* wb1 = swt + (size_t)((oc0 + 1) * 17) * 9;

    for (int py = 0; py < 7; py++) {
        ull acc[2][2][7];
        #pragma unroll
        for (int a = 0; a < 2; a++)
            #pragma unroll
            for (int d = 0; d < 2; d++)
                #pragma unroll
                for (int px = 0; px < 7; px++) acc[a][d][px] = 0ULL;

        for (int ic = 0; ic < 17; ic++) {
            ull W0[9], W1[9];
            #pragma unroll
            for (int j = 0; j < 9; j++) { W0[j] = wb0[ic * 9 + j]; W1[j] = wb1[ic * 9 + j]; }
            const float* rowp = tin + ic * 256 + 2 * py * 16;

            #pragma unroll
            for (int rr = 0; rr < 4; rr++) {
                float4 q0 = *(const float4*)(rowp + rr * 16 + 0);
                float4 q1 = *(const float4*)(rowp + rr * 16 + 4);
                float4 q2 = *(const float4*)(rowp + rr * 16 + 8);
                float4 q3 = *(const float4*)(rowp + rr * 16 + 12);
                ull E[8], O[7];
                E[0] = pk2(q0.x, q0.y); E[1] = pk2(q0.z, q0.w);
                E[2] = pk2(q1.x, q1.y); E[3] = pk2(q1.z, q1.w);
                E[4] = pk2(q2.x, q2.y); E[5] = pk2(q2.z, q2.w);
                E[6] = pk2(q3.x, q3.y); E[7] = pk2(q3.z, q3.w);
                O[0] = pk2(q0.y, q0.z); O[1] = pk2(q0.w, q1.x);
                O[2] = pk2(q1.y, q1.z); O[3] = pk2(q1.w, q2.x);
                O[4] = pk2(q2.y, q2.z); O[5] = pk2(q2.w, q3.x);
                O[6] = pk2(q3.y, q3.z);

                #define APPLY(dy, ky) do {                                          \
                    ull wA0 = W0[(ky)*3+0], wA1 = W1[(ky)*3+0];                     \
                    ull wBq0 = W0[(ky)*3+1], wBq1 = W1[(ky)*3+1];                   \
                    ull wC0 = W0[(ky)*3+2], wC1 = W1[(ky)*3+2];                     \
                    _Pragma("unroll")                                               \
                    for (int px = 0; px < 7; px++) {                                \
                        fma2(acc[0][dy][px], E[px],   wA0);                         \
                        fma2(acc[1][dy][px], E[px],   wA1);                         \
                        fma2(acc[0][dy][px], O[px],   wBq0);                        \
                        fma2(acc[1][dy][px], O[px],   wBq1);                        \
                        fma2(acc[0][dy][px], E[px+1], wC0);                         \
                        fma2(acc[1][dy][px], E[px+1], wC1);                         \
                    }                                                               \
                } while (0)

                if (rr <= 2) APPLY(0, rr);        // dy=0, ky=rr
                if (rr >= 1) APPLY(1, rr - 1);    // dy=1, ky=rr-1
                #undef APPLY
            }
        }
        // pool max over (dy,dx) + bias + relu
        #pragma unroll
        for (int px = 0; px < 7; px++) {
            float2 a0 = upk2(acc[0][0][px]), a1 = upk2(acc[0][1][px]);
            float m0 = fmaxf(fmaxf(a0.x, a0.y), fmaxf(a1.x, a1.y));
            outp[oc0 * 49 + py * 7 + px] = fmaxf(m0 + bb0, 0.0f);
            float2 c0 = upk2(acc[1][0][px]), c1 = upk2(acc[1][1][px]);
            float m1 = fmaxf(fmaxf(c0.x, c0.y), fmaxf(c1.x, c1.y));
            outp[(oc0 + 1) * 49 + py * 7 + px] = fmaxf(m1 + bb1, 0.0f);
        }
    }
}

// ---------------------------------------------------------------------------
// Kernel 2: fused fc1 (3136->128) + relu + fc2 (128->10).
// BM=32 -> grid 128 (one wave). BK=32, 256 threads, tile 4x4, f32x2,
// register-prefetch double buffering.
// ---------------------------------------------------------------------------
#define FCBM 32
__global__ void __launch_bounds__(256) fc_kernel(const float* __restrict__ w1,
                                                 const float* __restrict__ b1,
                                                 const float* __restrict__ w2,
                                                 const float* __restrict__ b2,
                                                 float* __restrict__ out) {
    __shared__ float sAT[32 * 36];     // [kk][row], stride 36 (16B-aligned reads)
    __shared__ float sB[32 * 132];     // [kk][n],  stride 132; reused as sC
    __shared__ float sw2[10 * 128];
    __shared__ float sb1v[128];

    int t  = threadIdx.x;
    int m0 = blockIdx.x * FCBM;
    int rg = t >> 5;                   // warp id -> rows rg*4..+3 (warp-uniform)
    int cg = t & 31;                   // cols cg*4..+3

    for (int i = t; i < 1280; i += 256) sw2[i] = w2[i];
    if (t < 128) sb1v[t] = b1[t];

    int arow = t >> 3, akk = (t & 7) * 4;
    int bn   = t >> 1, bkk = (t & 1) * 16;
    const float* Ap = g_pool2 + (size_t)(m0 + arow) * 3136 + akk;
    const float* Bp = w1 + (size_t)bn * 3136 + bkk;

    ull acc[4][2];
    #pragma unroll
    for (int i = 0; i < 4; i++) { acc[i][0] = 0ULL; acc[i][1] = 0ULL; }

    float4 ra  = *(const float4*)(Ap);
    float4 rb0 = *(const float4*)(Bp);
    float4 rb1 = *(const float4*)(Bp + 4);
    float4 rb2 = *(const float4*)(Bp + 8);
    float4 rb3 = *(const float4*)(Bp + 12);

    for (int k0 = 0; k0 < 3136; k0 += 32) {
        // commit prefetched tile to smem
        sAT[(akk + 0) * 36 + arow] = ra.x;
        sAT[(akk + 1) * 36 + arow] = ra.y;
        sAT[(akk + 2) * 36 + arow] = ra.z;
        sAT[(akk + 3) * 36 + arow] = ra.w;
        sB[(bkk + 0)  * 132 + bn] = rb0.x;  sB[(bkk + 1)  * 132 + bn] = rb0.y;
        sB[(bkk + 2)  * 132 + bn] = rb0.z;  sB[(bkk + 3)  * 132 + bn] = rb0.w;
        sB[(bkk + 4)  * 132 + bn] = rb1.x;  sB[(bkk + 5)  * 132 + bn] = rb1.y;
        sB[(bkk + 6)  * 132 + bn] = rb1.z;  sB[(bkk + 7)  * 132 + bn] = rb1.w;
        sB[(bkk + 8)  * 132 + bn] = rb2.x;  sB[(bkk + 9)  * 132 + bn] = rb2.y;
        sB[(bkk + 10) * 132 + bn] = rb2.z;  sB[(bkk + 11) * 132 + bn] = rb2.w;
        sB[(bkk + 12) * 132 + bn] = rb3.x;  sB[(bkk + 13) * 132 + bn] = rb3.y;
        sB[(bkk + 14) * 132 + bn] = rb3.z;  sB[(bkk + 15) * 132 + bn] = rb3.w;
        __syncthreads();
        // prefetch next k-block (overlaps compute)
        if (k0 + 32 < 3136) {
            ra  = *(const float4*)(Ap + k0 + 32);
            rb0 = *(const float4*)(Bp + k0 + 32);
            rb1 = *(const float4*)(Bp + k0 + 36);
            rb2 = *(const float4*)(Bp + k0 + 40);
            rb3 = *(const float4*)(Bp + k0 + 44);
        }
        #pragma unroll
        for (int kk = 0; kk < 32; kk++) {
            float4 av = *(const float4*)&sAT[kk * 36 + rg * 4];   // broadcast
            float4 bv = *(const float4*)&sB[kk * 132 + cg * 4];
            ull b01 = pk2(bv.x, bv.y), b23 = pk2(bv.z, bv.w);
            ull a;
            a = dup2(av.x); fma2(acc[0][0], a, b01); fma2(acc[0][1], a, b23);
            a = dup2(av.y); fma2(acc[1][0], a, b01); fma2(acc[1][1], a, b23);
            a = dup2(av.z); fma2(acc[2][0], a, b01); fma2(acc[2][1], a, b23);
            a = dup2(av.w); fma2(acc[3][0], a, b01); fma2(acc[3][1], a, b23);
        }
        __syncthreads();
    }

    // relu(fc1) -> sC (reuse sB, stride 132)
    float* sC = sB;
    #pragma unroll
    for (int i = 0; i < 4; i++) {
        int row = rg * 4 + i, col = cg * 4;
        float2 c0 = upk2(acc[i][0]);
        float2 c1 = upk2(acc[i][1]);
        sC[row * 132 + col + 0] = fmaxf(c0.x + sb1v[col + 0], 0.0f);
        sC[row * 132 + col + 1] = fmaxf(c0.y + sb1v[col + 1], 0.0f);
        sC[row * 132 + col + 2] = fmaxf(c1.x + sb1v[col + 2], 0.0f);
        sC[row * 132 + col + 3] = fmaxf(c1.y + sb1v[col + 3], 0.0f);
    }
    __syncthreads();
    // fc2 epilogue: 32 rows x 10 outputs
    for (int task = t; task < FCBM * 10; task += 256) {
        int row = task / 10, o = task % 10;
        const float* wr = sw2 + o * 128;
        float s = 0.0f;
        #pragma unroll 16
        for (int k = 0; k < 128; k++) s += sC[row * 132 + k] * wr[k];
        out[(size_t)(m0 + row) * 10 + o] = s + b2[o];
    }
}

// ---------------------------------------------------------------------------
extern "C" void kernel_launch(void* const* d_in, const int* in_sizes, int n_in,
                              void* d_out, int out_size) {
    const float* x       = (const float*)d_in[0];
    const float* theta   = (const float*)d_in[1];
    const float* sigma   = (const float*)d_in[2];
    const float* gamma   = (const float*)d_in[3];
    const float* lambd   = (const float*)d_in[4];
    const float* psi     = (const float*)d_in[5];
    const float* conv2_w = (const float*)d_in[6];
    const float* conv2_b = (const float*)d_in[7];
    const float* fc1_w   = (const float*)d_in[8];
    const float* fc1_b   = (const float*)d_in[9];
    const float* fc2_w   = (const float*)d_in[10];
    const float* fc2_b   = (const float*)d_in[11];
    float* out = (float*)d_out;

    const int CONV_SMEM = TILEF * 4 + WCNT * 8;   // 139392 + 78336 = 217728 B

    static bool attr_set = false;
    if (!attr_set) {
        cudaFuncSetAttribute(conv12_kernel,
                             cudaFuncAttributeMaxDynamicSharedMemorySize, CONV_SMEM);
        attr_set = true;
    }

    gabor_kernel<<<1, 160>>>(theta, sigma, gamma, lambd, psi);
    prep_w2_kernel<<<3, 256>>>(conv2_w);
    conv12_kernel<<<NBLK, 256, CONV_SMEM>>>(x, conv2_b);
    fc_kernel<<<BATCH / FCBM, 256>>>(fc1_w, fc1_b, fc2_w, fc2_b, out);
}